// round 3
// baseline (speedup 1.0000x reference)
#include <cuda_runtime.h>

#define T_STEPS 512
#define BATCH   512
#define SDIM    64
#define HID     128
#define ADIM    10

#define NCTA    128
#define NTHR    512
#define CLUSTER 8
#define BPC     32
#define KA      192   // layer0: k 0..127 = h0 (W_hh0), 128..191 = x (W_ih0)
#define KB      256   // layer1: k 0..127 = h0 (W_ih1), 128..255 = h1 (W_hh1)

// smem float offsets
#define SZ_WA   (16*2*KA*2)        // 12288
#define SZ_WB   (16*2*KB*2)        // 16384
#define SZ_WO   (HID*ADIM)         // 1280
#define OFF_WA  0
#define OFF_WB  12288
#define OFF_WO  28672
#define OFF_BIAS 29952             // 64 u64 = 128 floats
#define OFF_IN  30080              // [k][b] duplicated f32x2, k<320
#define SZ_IN   (320*64)           // 20480 floats
#define SMEM_BYTES ((OFF_IN + SZ_IN)*4)   // 202240

typedef unsigned long long u64;

// ping-pong hidden state, [j][b] layout
__device__ float g_h0[2][HID*BATCH];
__device__ float g_h1[2][HID*BATCH];

__device__ __forceinline__ float tanh_fast(float v) {
    float r; asm("tanh.approx.f32 %0, %1;" : "=f"(r) : "f"(v)); return r;
}
__device__ __forceinline__ float sigmoid_fast(float v) {
    return 0.5f * tanh_fast(0.5f * v) + 0.5f;
}
__device__ __forceinline__ u64 ffma2(u64 a, u64 b, u64 c) {
    u64 d; asm("fma.rn.f32x2 %0, %1, %2, %3;" : "=l"(d) : "l"(a), "l"(b), "l"(c)); return d;
}
__device__ __forceinline__ u64 add2(u64 a, u64 b) {
    u64 d; asm("add.rn.f32x2 %0, %1, %2;" : "=l"(d) : "l"(a), "l"(b)); return d;
}
__device__ __forceinline__ u64 pack2(float lo, float hi) {
    u64 d; asm("mov.b64 %0, {%1, %2};" : "=l"(d) : "f"(lo), "f"(hi)); return d;
}
__device__ __forceinline__ void unpack2(u64 v, float& lo, float& hi) {
    asm("mov.b64 {%0, %1}, %2;" : "=f"(lo), "=f"(hi) : "l"(v));
}
__device__ __forceinline__ void cluster_arrive() {
    asm volatile("barrier.cluster.arrive.aligned;" ::: "memory");
}
__device__ __forceinline__ void cluster_wait() {
    asm volatile("barrier.cluster.wait.aligned;" ::: "memory");
}

__device__ __forceinline__ float lstm_epi(u64 aif, u64 ago, float& c) {
    float ai, af, ag, ao;
    unpack2(aif, ai, af);
    unpack2(ago, ag, ao);
    float iG = sigmoid_fast(ai), fG = sigmoid_fast(af);
    float gG = tanh_fast(ag),    oG = sigmoid_fast(ao);
    c = fG * c + iG * gG;
    return oG * tanh_fast(c);
}

// Partial GEMM: J=4 hidden units, KR k's. Weights gate-pair interleaved
// (lo,hi) per k; x duplicated f32x2 at sx[k*64 + 2b].
template<int KR, int JSTRIDE>
__device__ __forceinline__ void gemm_part(const float* __restrict__ wb,
                                          const float* __restrict__ sx, int b2,
                                          u64 aif[4], u64 ago[4])
{
    #pragma unroll 8
    for (int k = 0; k < KR; k += 2) {
        u64 x0 = *(const u64*)(sx + k*64 + b2);
        u64 x1 = *(const u64*)(sx + k*64 + 64 + b2);
        #pragma unroll
        for (int jj = 0; jj < 4; ++jj) {
            ulonglong2 w0 = *(const ulonglong2*)(wb + jj*JSTRIDE + 2*k);
            ulonglong2 w1 = *(const ulonglong2*)(wb + jj*JSTRIDE + JSTRIDE/2 + 2*k);
            aif[jj] = ffma2(w0.x, x0, aif[jj]);
            ago[jj] = ffma2(w1.x, x0, ago[jj]);
            aif[jj] = ffma2(w0.y, x1, aif[jj]);
            ago[jj] = ffma2(w1.y, x1, ago[jj]);
        }
    }
}

// Partial store: [widx = kg*4+jgrp][jj][b][pr] as u64 pairs (16B aligned).
__device__ __forceinline__ void store_parts(u64* __restrict__ sRed, int widx, int b,
                                            const u64 aif[4], const u64 ago[4])
{
    #pragma unroll
    for (int jj = 0; jj < 4; ++jj)
        *(ulonglong2*)&sRed[((widx*4 + jj)*32 + b)*2] = make_ulonglong2(aif[jj], ago[jj]);
}

// Owner (wid<4, jgrp=wid): sum 4 k-partials + bias, epilogue, write h.
__device__ __forceinline__ void reduce_epi(const u64* __restrict__ sRed,
                                           const u64* __restrict__ sBiasU, int layer,
                                           int jgrp, int b, float c[4],
                                           float* __restrict__ hdst, int j0)
{
    #pragma unroll
    for (int jj = 0; jj < 4; ++jj) {
        ulonglong2 p0 = *(const ulonglong2*)&sRed[(((0*4 + jgrp)*4 + jj)*32 + b)*2];
        ulonglong2 p1 = *(const ulonglong2*)&sRed[(((1*4 + jgrp)*4 + jj)*32 + b)*2];
        ulonglong2 p2 = *(const ulonglong2*)&sRed[(((2*4 + jgrp)*4 + jj)*32 + b)*2];
        ulonglong2 p3 = *(const ulonglong2*)&sRed[(((3*4 + jgrp)*4 + jj)*32 + b)*2];
        u64 aif = add2(add2(p0.x, p1.x), add2(p2.x, p3.x));
        u64 ago = add2(add2(p0.y, p1.y), add2(p2.y, p3.y));
        aif = add2(aif, sBiasU[layer*32 + (jgrp*4 + jj)*2 + 0]);
        ago = add2(ago, sBiasU[layer*32 + (jgrp*4 + jj)*2 + 1]);
        hdst[(j0 + jgrp*4 + jj)*BATCH] = lstm_epi(aif, ago, c[jj]);
    }
}

__global__ void __cluster_dims__(CLUSTER, 1, 1) __launch_bounds__(NTHR, 1)
lstm_cluster(const float* __restrict__ x,
             const float* __restrict__ W_ih0, const float* __restrict__ W_hh0,
             const float* __restrict__ b_ih0, const float* __restrict__ b_hh0,
             const float* __restrict__ W_ih1, const float* __restrict__ W_hh1,
             const float* __restrict__ b_ih1, const float* __restrict__ b_hh1,
             const float* __restrict__ W_out, const float* __restrict__ b_out,
             float* __restrict__ out)
{
    extern __shared__ float smem[];
    float* sWA   = smem + OFF_WA;
    float* sWB   = smem + OFF_WB;
    float* sWO   = smem + OFF_WO;
    u64*   sBiasU= (u64*)(smem + OFF_BIAS);
    float* sIn   = smem + OFF_IN;
    u64*   sRed  = (u64*)(sIn + 128*64);    // overlays region1 (32KB)

    const int tid  = threadIdx.x;
    const int bid  = blockIdx.x;
    const int hs   = bid & (CLUSTER - 1);
    const int bs   = bid >> 3;
    const int j0   = hs * 16;
    const int b0   = bs * BPC;
    const int b    = tid & 31;              // lane = batch
    const int wid  = tid >> 5;
    const int jgrp = wid & 3;               // hidden group (4 j each)
    const int kg   = wid >> 2;              // k group (quarter)
    const int widx = kg*4 + jgrp;
    const int b2   = 2 * b;

    // ---- weights to smem: sW[((j*2+gp)*K + k)*2 + p], gate = gp*2+p (i,f,g,o) ----
    for (int idx = tid; idx < SZ_WA; idx += NTHR) {
        int p = idx & 1, r = idx >> 1;
        int k = r % KA; int r2 = r / KA;
        int gp = r2 & 1; int j = r2 >> 1;
        int row = (gp*2 + p) * HID + j0 + j;
        sWA[idx] = (k < HID) ? W_hh0[row*HID + k] : W_ih0[row*SDIM + (k - HID)];
    }
    for (int idx = tid; idx < SZ_WB; idx += NTHR) {
        int p = idx & 1, r = idx >> 1;
        int k = r % KB; int r2 = r / KB;
        int gp = r2 & 1; int j = r2 >> 1;
        int row = (gp*2 + p) * HID + j0 + j;
        sWB[idx] = (k < HID) ? W_ih1[row*HID + k] : W_hh1[row*HID + (k - HID)];
    }
    for (int idx = tid; idx < SZ_WO; idx += NTHR) {
        int j = idx / ADIM, a = idx - j*ADIM;
        sWO[idx] = W_out[a*HID + j];        // transposed [j][a]
    }
    // biases: sBiasU[layer*32 + j*2 + pr] = (b_lo, b_hi), pr0=(i,f) pr1=(g,o)
    if (tid < 64) {
        int layer = tid >> 5, r = tid & 31, j = r >> 1, pr = r & 1;
        int jg2 = j0 + j;
        int glo = pr*2, ghi = pr*2 + 1;
        float lo, hi;
        if (layer == 0) {
            lo = b_ih0[glo*HID + jg2] + b_hh0[glo*HID + jg2];
            hi = b_ih0[ghi*HID + jg2] + b_hh0[ghi*HID + jg2];
        } else {
            lo = b_ih1[glo*HID + jg2] + b_hh1[glo*HID + jg2];
            hi = b_ih1[ghi*HID + jg2] + b_hh1[ghi*HID + jg2];
        }
        sBiasU[layer*32 + j*2 + pr] = pack2(lo, hi);
    }

    // head constants (threads 0..39)
    const int lb  = tid / ADIM;
    const int ha  = tid - lb * ADIM;
    const int hbb = hs * 4 + lb;
    float bout_r = (tid < 4*ADIM) ? b_out[ha] : 0.0f;

    // zero h1(-1) (slot 1): this CTA's tile
    g_h1[1][(j0 + wid) * BATCH + b0 + b] = 0.0f;

    // ---- prologue: compute L0(0) ----
    #pragma unroll
    for (int i = 0; i < 8; ++i) {           // region0 = h0(-1) = 0
        int idx = tid + i*NTHR; int bb = idx & 31; int k = idx >> 5;
        *(float2*)&sIn[(k*32 + bb)*2] = make_float2(0.f, 0.f);
    }
    {                                       // region2 = x(0): float4 LDG, lane-minor STS
        float4 xr = *(const float4*)&x[((size_t)0*BATCH + b0 + b)*SDIM + wid*4];
        #pragma unroll
        for (int i = 0; i < 4; ++i) {
            float v = (&xr.x)[i];
            *(float2*)&sIn[((256 + wid*4 + i)*32 + b)*2] = make_float2(v, v);
        }
    }
    __syncthreads();

    float c0[4] = {0.f,0.f,0.f,0.f}, c1[4] = {0.f,0.f,0.f,0.f};
    {
        u64 aif[4] = {0,0,0,0}, ago[4] = {0,0,0,0};
        gemm_part<32, 768>(sWA + (jgrp*4)*768 + (kg*32)*2, sIn + (kg*32)*64, b2, aif, ago);
        gemm_part<16, 768>(sWA + (jgrp*4)*768 + (128 + kg*16)*2, sIn + (256 + kg*16)*64, b2, aif, ago);
        __syncthreads();
        store_parts(sRed, widx, b, aif, ago);
        __syncthreads();
        if (wid < 4)
            reduce_epi(sRed, sBiasU, 0, jgrp, b, c0, &g_h0[0][b0 + b], j0);
    }
    cluster_arrive();

    // ---- main loop ----
    for (int t = 0; t < T_STEPS; ++t) {
        const int sc = t & 1;
        const float* h0src = g_h0[sc];       // h0(t)
        const float* h1src = g_h1[sc ^ 1];   // h1(t-1)

        // x(t+1) prefetch (independent of barrier)
        float4 xr = make_float4(0.f,0.f,0.f,0.f);
        if (t < T_STEPS - 1)
            xr = *(const float4*)&x[((size_t)(t+1)*BATCH + b0 + b)*SDIM + wid*4];

        cluster_wait();                      // h0(t), h1(t-1) ready

        #pragma unroll
        for (int i = 0; i < 8; ++i) {        // region0 = h0(t)
            int idx = tid + i*NTHR; int bb = idx & 31; int k = idx >> 5;
            float v = __ldcg(&h0src[k*BATCH + b0 + bb]);
            *(float2*)&sIn[(k*32 + bb)*2] = make_float2(v, v);
        }
        #pragma unroll
        for (int i = 0; i < 8; ++i) {        // region1 = h1(t-1)
            int idx = tid + i*NTHR; int bb = idx & 31; int k = idx >> 5;
            float v = __ldcg(&h1src[k*BATCH + b0 + bb]);
            *(float2*)&sIn[((128 + k)*32 + bb)*2] = make_float2(v, v);
        }
        if (t < T_STEPS - 1) {
            #pragma unroll
            for (int i = 0; i < 4; ++i) {    // region2 = x(t+1)
                float v = (&xr.x)[i];
                *(float2*)&sIn[((256 + wid*4 + i)*32 + b)*2] = make_float2(v, v);
            }
        }
        __syncthreads();

        // L1(t) partial: K = [h0(t) | h1(t-1)]
        u64 aif[4] = {0,0,0,0}, ago[4] = {0,0,0,0};
        gemm_part<64, 1024>(sWB + (jgrp*4)*1024 + (kg*64)*2, sIn + (kg*64)*64, b2, aif, ago);

        // output head for t-1 (reads region1 before sRed overwrites it)
        if (t > 0 && tid < 4*ADIM) {
            float s = bout_r;
            #pragma unroll 8
            for (int j = 0; j < HID; ++j)
                s = fmaf(sIn[((128 + j)*32 + hbb)*2], sWO[j*ADIM + ha], s);
            out[((size_t)(t-1)*BATCH + b0 + hbb)*ADIM + ha] = tanh_fast(s);
        }
        __syncthreads();                     // gemm+head reads of region1 done
        store_parts(sRed, widx, b, aif, ago);
        __syncthreads();
        if (wid < 4)
            reduce_epi(sRed, sBiasU, 1, jgrp, b, c1, &g_h1[sc][b0 + b], j0);

        // L0(t+1) partial: K = [h0(t) (region0) | x(t+1) (region2)]
        if (t < T_STEPS - 1) {
            u64 af2[4] = {0,0,0,0}, ag2[4] = {0,0,0,0};
            gemm_part<32, 768>(sWA + (jgrp*4)*768 + (kg*32)*2, sIn + (kg*32)*64, b2, af2, ag2);
            gemm_part<16, 768>(sWA + (jgrp*4)*768 + (128 + kg*16)*2, sIn + (256 + kg*16)*64, b2, af2, ag2);
            __syncthreads();                 // owners' L1-partial reads done
            store_parts(sRed, widx, b, af2, ag2);
            __syncthreads();
            if (wid < 4)
                reduce_epi(sRed, sBiasU, 0, jgrp, b, c0, &g_h0[sc ^ 1][b0 + b], j0);
        }

        cluster_arrive();                    // release: h1(t), h0(t+1) visible
    }

    cluster_wait();

    // final head: t = T-1, h1(511) in slot 1
    if (tid < 4*ADIM) {
        float s = bout_r;
        const float* hp = &g_h1[1][b0 + hbb];
        #pragma unroll 8
        for (int j = 0; j < HID; ++j)
            s = fmaf(__ldcg(&hp[j*BATCH]), sWO[j*ADIM + ha], s);
        out[((size_t)(T_STEPS-1)*BATCH + b0 + hbb)*ADIM + ha] = tanh_fast(s);
    }
}

extern "C" void kernel_launch(void* const* d_in, const int* in_sizes, int n_in,
                              void* d_out, int out_size)
{
    const float* x    = (const float*)d_in[0];
    const float* Wih0 = (const float*)d_in[1];
    const float* Whh0 = (const float*)d_in[2];
    const float* bih0 = (const float*)d_in[3];
    const float* bhh0 = (const float*)d_in[4];
    const float* Wih1 = (const float*)d_in[5];
    const float* Whh1 = (const float*)d_in[6];
    const float* bih1 = (const float*)d_in[7];
    const float* bhh1 = (const float*)d_in[8];
    const float* Wout = (const float*)d_in[9];
    const float* bout = (const float*)d_in[10];
    float* out = (float*)d_out;

    cudaFuncSetAttribute(lstm_cluster,
                         cudaFuncAttributeMaxDynamicSharedMemorySize, SMEM_BYTES);

    lstm_cluster<<<NCTA, NTHR, SMEM_BYTES>>>(
        x, Wih0, Whh0, bih0, bhh0, Wih1, Whh1, bih1, bhh1, Wout, bout, out);
}

// round 4
// speedup vs baseline: 1.7980x; 1.7980x over previous
#include <cuda_runtime.h>
#include <cstdint>

#define T_STEPS 512
#define BATCH   512
#define SDIM    64
#define HID     128
#define ADIM    10

#define NCTA    128
#define NTHR    256
#define CLUSTER 8
#define KA      192    // layer0: k 0..127 = h0(t-1) (W_hh0), 128..191 = x(t) (W_ih0)
#define KB      256    // layer1: k 0..127 = h0(t)   (W_ih1), 128..255 = h1(t-1) (W_hh1)

// float offsets within dynamic smem
#define OFF_MBAR 0       // 2 u64 mbarriers (A at +0, B at +8 bytes), pad to 8 floats
#define OFF_BIAS 8       // 64 u64: [layer(2)][jl(16)][pr(2)]
#define OFF_WO   136     // 640 u64: [j(128)][ap(5)] = (W_out[2ap][j], W_out[2ap+1][j])
#define OFF_WA   1416    // 12288 floats
#define OFF_WB   13704   // 16384 floats
#define OFF_R0   30088   // 2 bufs x 4096 floats: h0 [kp(64)][b(32)][2]
#define OFF_R1   38280   // 2 bufs x 4096 floats: h1
#define OFF_X    46472   // 2 bufs x 2048 floats: x  [kp(32)][b(32)][2]
#define SMEM_FLOATS 50568
#define SMEM_BYTES (SMEM_FLOATS*4)   // 202272

typedef unsigned long long u64;
typedef unsigned int u32;

__device__ __forceinline__ float tanh_fast(float v) {
    float r; asm("tanh.approx.f32 %0, %1;" : "=f"(r) : "f"(v)); return r;
}
__device__ __forceinline__ float sigmoid_fast(float v) {
    return 0.5f * tanh_fast(0.5f * v) + 0.5f;
}
__device__ __forceinline__ u64 ffma2(u64 a, u64 b, u64 c) {
    u64 d; asm("fma.rn.f32x2 %0, %1, %2, %3;" : "=l"(d) : "l"(a), "l"(b), "l"(c)); return d;
}
__device__ __forceinline__ u64 pack2(float lo, float hi) {
    u64 d; asm("mov.b64 %0, {%1, %2};" : "=l"(d) : "f"(lo), "f"(hi)); return d;
}
__device__ __forceinline__ void unpack2(u64 v, float& lo, float& hi) {
    asm("mov.b64 {%0, %1}, %2;" : "=f"(lo), "=f"(hi) : "l"(v));
}
__device__ __forceinline__ u32 smem_u32(const void* p) {
    u32 a; asm("{ .reg .u64 t; cvta.to.shared.u64 t, %1; cvt.u32.u64 %0, t; }" : "=r"(a) : "l"(p));
    return a;
}
__device__ __forceinline__ void cluster_sync() {
    asm volatile("barrier.cluster.arrive.aligned;" ::: "memory");
    asm volatile("barrier.cluster.wait.aligned;"   ::: "memory");
}
__device__ __forceinline__ void mbar_wait(u32 mb, u32 parity) {
    asm volatile(
        "{ .reg .pred P;\n\t"
        "W%=: mbarrier.try_wait.parity.acquire.cluster.shared::cta.b64 P, [%0], %1, 0x989680;\n\t"
        "@P bra D%=;\n\t"
        "bra W%=;\n\t"
        "D%=: }"
        :: "r"(mb), "r"(parity) : "memory");
}
// push one u64 (pair of h values) into the same smem slot of all 8 cluster CTAs,
// each store signaling that CTA's mbarrier with 8 tx bytes.
__device__ __forceinline__ void push_pair(u32 dst_local, u64 val, u32 mb_local) {
    #pragma unroll
    for (int r = 0; r < CLUSTER; ++r) {
        u32 d, m;
        asm("mapa.shared::cluster.u32 %0, %1, %2;" : "=r"(d) : "r"(dst_local), "r"(r));
        asm("mapa.shared::cluster.u32 %0, %1, %2;" : "=r"(m) : "r"(mb_local), "r"(r));
        asm volatile("st.async.shared::cluster.mbarrier::complete_tx::bytes.b64 [%0], %1, [%2];"
                     :: "r"(d), "l"(val), "r"(m) : "memory");
    }
}

__device__ __forceinline__ float lstm_epi(u64 aif, u64 ago, float& c) {
    float ai, af, ag, ao;
    unpack2(aif, ai, af);
    unpack2(ago, ag, ao);
    float iG = sigmoid_fast(ai), fG = sigmoid_fast(af);
    float gG = tanh_fast(ag),    oG = sigmoid_fast(ao);
    c = fG * c + iG * gG;
    return oG * tanh_fast(c);
}

// GEMM block: KP k-pairs. Weights at wbase: per kp, 16 floats =
// [k0: j0if j0go j1if j1go][k1: ...] as u64 gate-pairs. x at xbase (+b*8 lane).
template<int KP>
__device__ __forceinline__ void gemm_blk(u32 wbase, u32 xbase,
                                         u64& a0, u64& a1, u64& a2, u64& a3)
{
    #pragma unroll 8
    for (int kp = 0; kp < KP; ++kp) {
        float x0, x1;
        asm("ld.shared.v2.f32 {%0,%1}, [%2];" : "=f"(x0), "=f"(x1) : "r"(xbase + kp*256));
        u64 X0 = pack2(x0, x0), X1 = pack2(x1, x1);
        u64 wa0, wa1, wb0, wb1, wc0, wc1, wd0, wd1;
        asm("ld.shared.v2.b64 {%0,%1}, [%2];" : "=l"(wa0), "=l"(wa1) : "r"(wbase + kp*64));
        asm("ld.shared.v2.b64 {%0,%1}, [%2];" : "=l"(wb0), "=l"(wb1) : "r"(wbase + kp*64 + 16));
        asm("ld.shared.v2.b64 {%0,%1}, [%2];" : "=l"(wc0), "=l"(wc1) : "r"(wbase + kp*64 + 32));
        asm("ld.shared.v2.b64 {%0,%1}, [%2];" : "=l"(wd0), "=l"(wd1) : "r"(wbase + kp*64 + 48));
        a0 = ffma2(wa0, X0, a0);  a1 = ffma2(wa1, X0, a1);
        a2 = ffma2(wb0, X0, a2);  a3 = ffma2(wb1, X0, a3);
        a0 = ffma2(wc0, X1, a0);  a1 = ffma2(wc1, X1, a1);
        a2 = ffma2(wd0, X1, a2);  a3 = ffma2(wd1, X1, a3);
    }
}

__global__ void __cluster_dims__(CLUSTER, 1, 1) __launch_bounds__(NTHR, 1)
lstm_dsmem(const float* __restrict__ x,
           const float* __restrict__ W_ih0, const float* __restrict__ W_hh0,
           const float* __restrict__ b_ih0, const float* __restrict__ b_hh0,
           const float* __restrict__ W_ih1, const float* __restrict__ W_hh1,
           const float* __restrict__ b_ih1, const float* __restrict__ b_hh1,
           const float* __restrict__ W_out, const float* __restrict__ b_out,
           float* __restrict__ out)
{
    extern __shared__ float smem[];
    const u32 sb  = smem_u32(smem);
    const int tid = threadIdx.x;
    const int bid = blockIdx.x;
    const int hs  = bid & (CLUSTER - 1);   // hidden slice = cluster rank
    const int bs  = bid >> 3;              // batch slice (shared by cluster)
    const int j0  = hs * 16;
    const int b0  = bs * 32;
    const int b   = tid & 31;              // lane = batch
    const int wid = tid >> 5;              // warp = j-pair (8 warps x 2 j = 16)

    const u32 mbA = sb + OFF_MBAR * 4;
    const u32 mbB = sb + OFF_MBAR * 4 + 8;

    // ---- weights layer0 -> smem (interleaved gate-pair layout) ----
    for (int idx = tid; idx < 12288; idx += NTHR) {
        int p  = idx & 1, pr = (idx >> 1) & 1, jl = (idx >> 2) & 1, kk = (idx >> 3) & 1;
        int rest = idx >> 4;
        int kp = rest % 96, jp = rest / 96;
        int k = kp * 2 + kk;
        int gate = pr * 2 + p;
        int row = gate * HID + j0 + jp * 2 + jl;
        smem[OFF_WA + idx] = (k < HID) ? W_hh0[row * HID + k]
                                       : W_ih0[row * SDIM + (k - HID)];
    }
    // ---- weights layer1 ----
    for (int idx = tid; idx < 16384; idx += NTHR) {
        int p  = idx & 1, pr = (idx >> 1) & 1, jl = (idx >> 2) & 1, kk = (idx >> 3) & 1;
        int rest = idx >> 4;
        int kp = rest % 128, jp = rest / 128;
        int k = kp * 2 + kk;
        int gate = pr * 2 + p;
        int row = gate * HID + j0 + jp * 2 + jl;
        smem[OFF_WB + idx] = (k < HID) ? W_ih1[row * HID + k]
                                       : W_hh1[row * HID + (k - HID)];
    }
    // ---- biases: u64 (lo,hi) per (layer, jl, pr) ----
    if (tid < 64) {
        int layer = tid >> 5, r = tid & 31, jl = r >> 1, pr = r & 1;
        int jg = j0 + jl;
        int glo = pr * 2, ghi = pr * 2 + 1;
        float lo, hi;
        if (layer == 0) {
            lo = b_ih0[glo*HID + jg] + b_hh0[glo*HID + jg];
            hi = b_ih0[ghi*HID + jg] + b_hh0[ghi*HID + jg];
        } else {
            lo = b_ih1[glo*HID + jg] + b_hh1[glo*HID + jg];
            hi = b_ih1[ghi*HID + jg] + b_hh1[ghi*HID + jg];
        }
        ((u64*)(smem + OFF_BIAS))[layer*32 + jl*2 + pr] = pack2(lo, hi);
    }
    // ---- head weights: [j][ap] u64 ----
    for (int idx = tid; idx < 640; idx += NTHR) {
        int j = idx / 5, ap = idx - j*5;
        ((u64*)(smem + OFF_WO))[idx] = pack2(W_out[(2*ap)*HID + j], W_out[(2*ap+1)*HID + j]);
    }
    // ---- zero buf1 of R0/R1 (h0(-1) = h1(-1) = 0) ----
    for (int idx = tid; idx < 4096; idx += NTHR) {
        smem[OFF_R0 + 4096 + idx] = 0.0f;
        smem[OFF_R1 + 4096 + idx] = 0.0f;
    }
    // ---- stage x(0) into sX[0] ----
    {
        const float4* xp = (const float4*)&x[((size_t)0*BATCH + b0 + b)*SDIM + wid*8];
        float4 xa = xp[0], xb2 = xp[1];
        float* xd = smem + OFF_X + ((wid*4)*32 + b)*2;
        *(float2*)(xd      ) = make_float2(xa.x, xa.y);
        *(float2*)(xd +  64) = make_float2(xa.z, xa.w);
        *(float2*)(xd + 128) = make_float2(xb2.x, xb2.y);
        *(float2*)(xd + 192) = make_float2(xb2.z, xb2.w);
    }
    // ---- mbarrier init (count = 1: the per-step expect_tx arrival) ----
    if (tid == 0) {
        asm volatile("mbarrier.init.shared.b64 [%0], 1;" :: "r"(mbA) : "memory");
        asm volatile("mbarrier.init.shared.b64 [%0], 1;" :: "r"(mbB) : "memory");
    }
    __syncthreads();
    cluster_sync();   // peers' mbarriers + buffers ready before any st.async

    // per-thread bias regs
    const u64* biasU = (const u64*)(smem + OFF_BIAS);
    const u64 bA0 = biasU[wid*4+0], bA1 = biasU[wid*4+1];
    const u64 bA2 = biasU[wid*4+2], bA3 = biasU[wid*4+3];
    const u64 bB0 = biasU[32+wid*4+0], bB1 = biasU[32+wid*4+1];
    const u64 bB2 = biasU[32+wid*4+2], bB3 = biasU[32+wid*4+3];
    const u64 houtb = (wid < 5) ? pack2(b_out[wid*2], b_out[wid*2+1]) : 0ull;

    const u32 wA   = sb + OFF_WA*4 + wid*6144;   // 96 kp x 64B
    const u32 wB   = sb + OFF_WB*4 + wid*8192;   // 128 kp x 64B
    const u32 lane8 = b * 8;
    const u32 pushOff = ((u32)(hs*8 + wid)*32 + b) * 8;   // byte offset in region buf

    float c00 = 0.f, c01 = 0.f, c10 = 0.f, c11 = 0.f;

    for (int t = 0; t < T_STEPS; ++t) {
        const u32 par  = (u32)(t & 1);
        const u32 r0rd = sb + (OFF_R0 + ((t+1)&1)*4096)*4;   // h0(t-1)
        const u32 r0wr = sb + (OFF_R0 + (t&1)*4096)*4;       // h0(t)
        const u32 r1rd = sb + (OFF_R1 + ((t+1)&1)*4096)*4;   // h1(t-1)
        const u32 r1wr = sb + (OFF_R1 + (t&1)*4096)*4;       // h1(t)
        const u32 xrd  = sb + (OFF_X  + (t&1)*2048)*4;       // x(t)

        if (tid == 0) {
            asm volatile("mbarrier.arrive.expect_tx.shared.b64 _, [%0], 16384;" :: "r"(mbA) : "memory");
            asm volatile("mbarrier.arrive.expect_tx.shared.b64 _, [%0], 16384;" :: "r"(mbB) : "memory");
        }

        // ---- L0(t): gates from [h0(t-1) | x(t)] ----
        {
            u64 a0 = bA0, a1 = bA1, a2 = bA2, a3 = bA3;
            gemm_blk<64>(wA,        r0rd + lane8, a0, a1, a2, a3);
            gemm_blk<32>(wA + 4096, xrd  + lane8, a0, a1, a2, a3);
            float h00 = lstm_epi(a0, a1, c00);
            float h01 = lstm_epi(a2, a3, c01);
            push_pair(r0wr + pushOff, pack2(h00, h01), mbA);
        }

        // ---- stage x(t+1) (overlaps with mbarA wait) ----
        if (t < T_STEPS - 1) {
            const float4* xp = (const float4*)&x[((size_t)(t+1)*BATCH + b0 + b)*SDIM + wid*8];
            float4 xa = xp[0], xb2 = xp[1];
            float* xd = smem + OFF_X + ((t+1)&1)*2048 + ((wid*4)*32 + b)*2;
            *(float2*)(xd      ) = make_float2(xa.x, xa.y);
            *(float2*)(xd +  64) = make_float2(xa.z, xa.w);
            *(float2*)(xd + 128) = make_float2(xb2.x, xb2.y);
            *(float2*)(xd + 192) = make_float2(xb2.z, xb2.w);
        }
        __syncthreads();            // drain x STS before next step's reads

        mbar_wait(mbA, par);        // h0(t) complete (all 128 j) in r0wr

        // ---- L1(t): gates from [h0(t) | h1(t-1)] ----
        {
            u64 a0 = bB0, a1 = bB1, a2 = bB2, a3 = bB3;
            gemm_blk<64>(wB,        r0wr + lane8, a0, a1, a2, a3);
            gemm_blk<64>(wB + 4096, r1rd + lane8, a0, a1, a2, a3);
            float h10 = lstm_epi(a0, a1, c10);
            float h11 = lstm_epi(a2, a3, c11);
            push_pair(r1wr + pushOff, pack2(h10, h11), mbB);
        }

        mbar_wait(mbB, par);        // h1(t) complete in r1wr

        // ---- head(t): out = tanh(h1(t) @ W_out^T + b_out) ----
        if (wid < 5) {
            u64 acc = houtb;
            const u32 wo = sb + OFF_WO*4 + wid*8;
            #pragma unroll 8
            for (int kp = 0; kp < 64; ++kp) {
                float h0v, h1v;
                asm("ld.shared.v2.f32 {%0,%1}, [%2];" : "=f"(h0v), "=f"(h1v)
                    : "r"(r1wr + lane8 + kp*256));
                u64 w0, w1;
                asm("ld.shared.b64 %0, [%1];" : "=l"(w0) : "r"(wo + kp*80));
                asm("ld.shared.b64 %0, [%1];" : "=l"(w1) : "r"(wo + kp*80 + 40));
                acc = ffma2(w0, pack2(h0v, h0v), acc);
                acc = ffma2(w1, pack2(h1v, h1v), acc);
            }
            float o0, o1; unpack2(acc, o0, o1);
            float2 ov = make_float2(tanh_fast(o0), tanh_fast(o1));
            *(float2*)&out[((size_t)t*BATCH + b0 + b)*ADIM + wid*2] = ov;
        }
    }

    cluster_sync();   // all deliveries drained before exit
}

extern "C" void kernel_launch(void* const* d_in, const int* in_sizes, int n_in,
                              void* d_out, int out_size)
{
    const float* x    = (const float*)d_in[0];
    const float* Wih0 = (const float*)d_in[1];
    const float* Whh0 = (const float*)d_in[2];
    const float* bih0 = (const float*)d_in[3];
    const float* bhh0 = (const float*)d_in[4];
    const float* Wih1 = (const float*)d_in[5];
    const float* Whh1 = (const float*)d_in[6];
    const float* bih1 = (const float*)d_in[7];
    const float* bhh1 = (const float*)d_in[8];
    const float* Wout = (const float*)d_in[9];
    const float* bout = (const float*)d_in[10];
    float* out = (float*)d_out;

    cudaFuncSetAttribute(lstm_dsmem,
                         cudaFuncAttributeMaxDynamicSharedMemorySize, SMEM_BYTES);

    lstm_dsmem<<<NCTA, NTHR, SMEM_BYTES>>>(
        x, Wih0, Whh0, bih0, bhh0, Wih1, Whh1, bih1, bhh1, Wout, bout, out);
}

// round 5
// speedup vs baseline: 1.8656x; 1.0375x over previous
#include <cuda_runtime.h>
#include <cstdint>

#define T_STEPS 512
#define BATCH   512
#define SDIM    64
#define HID     128
#define ADIM    10

#define NCTA    128
#define NTHR    256
#define CLUSTER 8

// float offsets within dynamic smem
#define OFF_MBAR 0       // 2 u64 mbarriers (A at +0, B at +8 bytes)
#define OFF_BIAS 8       // 64 u64: [layer(2)][jl(16)][pr(2)]
#define OFF_WO   136     // 640 u64: [j(128)][ap(5)]
#define OFF_WA   1416    // 12288 floats
#define OFF_WB   13704   // 16384 floats
#define OFF_R0   30088   // 2 bufs x 4096 floats: h0 [jp(64)][b(32)][2]
#define OFF_R1   38280   // 2 bufs x 4096 floats: h1
#define OFF_X    46472   // 2 bufs x 2048 floats: x  [kp(32)][b(32)][2]
#define OFF_STA  50568   // 2 bufs x 512 floats staging for A pushes
#define OFF_STB  51592   // 2 bufs x 512 floats staging for B pushes
#define SMEM_FLOATS 52616
#define SMEM_BYTES (SMEM_FLOATS*4)   // 210464

typedef unsigned long long u64;
typedef unsigned int u32;

__device__ __forceinline__ float tanh_fast(float v) {
    float r; asm("tanh.approx.f32 %0, %1;" : "=f"(r) : "f"(v)); return r;
}
__device__ __forceinline__ float sigmoid_fast(float v) {
    return 0.5f * tanh_fast(0.5f * v) + 0.5f;
}
__device__ __forceinline__ u64 ffma2(u64 a, u64 b, u64 c) {
    u64 d; asm("fma.rn.f32x2 %0, %1, %2, %3;" : "=l"(d) : "l"(a), "l"(b), "l"(c)); return d;
}
__device__ __forceinline__ u64 pack2(float lo, float hi) {
    u64 d; asm("mov.b64 %0, {%1, %2};" : "=l"(d) : "f"(lo), "f"(hi)); return d;
}
__device__ __forceinline__ void unpack2(u64 v, float& lo, float& hi) {
    asm("mov.b64 {%0, %1}, %2;" : "=f"(lo), "=f"(hi) : "l"(v));
}
__device__ __forceinline__ u32 smem_u32(const void* p) {
    u32 a; asm("{ .reg .u64 t; cvta.to.shared.u64 t, %1; cvt.u32.u64 %0, t; }" : "=r"(a) : "l"(p));
    return a;
}
__device__ __forceinline__ void cluster_sync() {
    asm volatile("barrier.cluster.arrive.aligned;" ::: "memory");
    asm volatile("barrier.cluster.wait.aligned;"   ::: "memory");
}
__device__ __forceinline__ bool elect1() {
    u32 p; asm volatile("{ .reg .pred p; elect.sync _|p, 0xFFFFFFFF; selp.b32 %0, 1, 0, p; }"
                        : "=r"(p)); return p != 0;
}
__device__ __forceinline__ void mbar_wait(u32 mb, u32 parity) {
    asm volatile(
        "{ .reg .pred P;\n\t"
        "W%=: mbarrier.try_wait.parity.acquire.cluster.shared::cta.b64 P, [%0], %1, 0x989680;\n\t"
        "@P bra D%=;\n\t"
        "bra W%=;\n\t"
        "D%=: }"
        :: "r"(mb), "r"(parity) : "memory");
}
__device__ __forceinline__ void mbar_expect(u32 mb, u32 bytes) {
    asm volatile("mbarrier.arrive.expect_tx.shared.b64 _, [%0], %1;"
                 :: "r"(mb), "r"(bytes) : "memory");
}
// Bulk-push 256B (one warp's h pairs) from local staging to the same region
// slot of all 8 cluster CTAs, signaling each CTA's mbarrier (+256 tx bytes).
__device__ __forceinline__ void push_bulk(u32 dst_local, u32 src_local, u32 mb_local) {
    asm volatile("fence.proxy.async.shared::cta;" ::: "memory");
    #pragma unroll
    for (int r = 0; r < CLUSTER; ++r) {
        u32 d, m;
        asm("mapa.shared::cluster.u32 %0, %1, %2;" : "=r"(d) : "r"(dst_local), "r"(r));
        asm("mapa.shared::cluster.u32 %0, %1, %2;" : "=r"(m) : "r"(mb_local), "r"(r));
        asm volatile(
            "cp.async.bulk.shared::cluster.shared::cta.mbarrier::complete_tx::bytes "
            "[%0], [%1], 256, [%2];"
            :: "r"(d), "r"(src_local), "r"(m) : "memory");
    }
}

__device__ __forceinline__ float lstm_epi(u64 aif, u64 ago, float& c) {
    float ai, af, ag, ao;
    unpack2(aif, ai, af);
    unpack2(ago, ag, ao);
    float iG = sigmoid_fast(ai), fG = sigmoid_fast(af);
    float gG = tanh_fast(ag),    oG = sigmoid_fast(ao);
    c = fG * c + iG * gG;
    return oG * tanh_fast(c);
}

// GEMM block: KP k-pairs. Weights at wbase: per kp, 64B = u64 gate-pairs
// [k0: j0if j0go j1if j1go][k1: ...]. x at xbase + b*8.
template<int KP>
__device__ __forceinline__ void gemm_blk(u32 wbase, u32 xbase,
                                         u64& a0, u64& a1, u64& a2, u64& a3)
{
    #pragma unroll 8
    for (int kp = 0; kp < KP; ++kp) {
        float x0, x1;
        asm("ld.shared.v2.f32 {%0,%1}, [%2];" : "=f"(x0), "=f"(x1) : "r"(xbase + kp*256));
        u64 X0 = pack2(x0, x0), X1 = pack2(x1, x1);
        u64 wa0, wa1, wb0, wb1, wc0, wc1, wd0, wd1;
        asm("ld.shared.v2.b64 {%0,%1}, [%2];" : "=l"(wa0), "=l"(wa1) : "r"(wbase + kp*64));
        asm("ld.shared.v2.b64 {%0,%1}, [%2];" : "=l"(wb0), "=l"(wb1) : "r"(wbase + kp*64 + 16));
        asm("ld.shared.v2.b64 {%0,%1}, [%2];" : "=l"(wc0), "=l"(wc1) : "r"(wbase + kp*64 + 32));
        asm("ld.shared.v2.b64 {%0,%1}, [%2];" : "=l"(wd0), "=l"(wd1) : "r"(wbase + kp*64 + 48));
        a0 = ffma2(wa0, X0, a0);  a1 = ffma2(wa1, X0, a1);
        a2 = ffma2(wb0, X0, a2);  a3 = ffma2(wb1, X0, a3);
        a0 = ffma2(wc0, X1, a0);  a1 = ffma2(wc1, X1, a1);
        a2 = ffma2(wd0, X1, a2);  a3 = ffma2(wd1, X1, a3);
    }
}

__global__ void __cluster_dims__(CLUSTER, 1, 1) __launch_bounds__(NTHR, 1)
lstm_dsmem(const float* __restrict__ x,
           const float* __restrict__ W_ih0, const float* __restrict__ W_hh0,
           const float* __restrict__ b_ih0, const float* __restrict__ b_hh0,
           const float* __restrict__ W_ih1, const float* __restrict__ W_hh1,
           const float* __restrict__ b_ih1, const float* __restrict__ b_hh1,
           const float* __restrict__ W_out, const float* __restrict__ b_out,
           float* __restrict__ out)
{
    extern __shared__ float smem[];
    const u32 sb  = smem_u32(smem);
    const int tid = threadIdx.x;
    const int bid = blockIdx.x;
    const int hs  = bid & (CLUSTER - 1);   // hidden slice = cluster rank
    const int bs  = bid >> 3;              // batch slice (shared by cluster)
    const int j0  = hs * 16;
    const int b0  = bs * 32;
    const int b   = tid & 31;              // lane = batch
    const int wid = tid >> 5;              // warp = j-pair (8 warps x 2 j = 16)

    const u32 mbA = sb + OFF_MBAR * 4;
    const u32 mbB = sb + OFF_MBAR * 4 + 8;

    // ---- weights layer0 -> smem (interleaved gate-pair layout) ----
    for (int idx = tid; idx < 12288; idx += NTHR) {
        int p  = idx & 1, pr = (idx >> 1) & 1, jl = (idx >> 2) & 1, kk = (idx >> 3) & 1;
        int rest = idx >> 4;
        int kp = rest % 96, jp = rest / 96;
        int k = kp * 2 + kk;
        int gate = pr * 2 + p;
        int row = gate * HID + j0 + jp * 2 + jl;
        smem[OFF_WA + idx] = (k < HID) ? W_hh0[row * HID + k]
                                       : W_ih0[row * SDIM + (k - HID)];
    }
    // ---- weights layer1 ----
    for (int idx = tid; idx < 16384; idx += NTHR) {
        int p  = idx & 1, pr = (idx >> 1) & 1, jl = (idx >> 2) & 1, kk = (idx >> 3) & 1;
        int rest = idx >> 4;
        int kp = rest % 128, jp = rest / 128;
        int k = kp * 2 + kk;
        int gate = pr * 2 + p;
        int row = gate * HID + j0 + jp * 2 + jl;
        smem[OFF_WB + idx] = (k < HID) ? W_ih1[row * HID + k]
                                       : W_hh1[row * HID + (k - HID)];
    }
    // ---- biases ----
    if (tid < 64) {
        int layer = tid >> 5, r = tid & 31, jl = r >> 1, pr = r & 1;
        int jg = j0 + jl;
        int glo = pr * 2, ghi = pr * 2 + 1;
        float lo, hi;
        if (layer == 0) {
            lo = b_ih0[glo*HID + jg] + b_hh0[glo*HID + jg];
            hi = b_ih0[ghi*HID + jg] + b_hh0[ghi*HID + jg];
        } else {
            lo = b_ih1[glo*HID + jg] + b_hh1[glo*HID + jg];
            hi = b_ih1[ghi*HID + jg] + b_hh1[ghi*HID + jg];
        }
        ((u64*)(smem + OFF_BIAS))[layer*32 + jl*2 + pr] = pack2(lo, hi);
    }
    // ---- head weights: [j][ap] u64 ----
    for (int idx = tid; idx < 640; idx += NTHR) {
        int j = idx / 5, ap = idx - j*5;
        ((u64*)(smem + OFF_WO))[idx] = pack2(W_out[(2*ap)*HID + j], W_out[(2*ap+1)*HID + j]);
    }
    // ---- zero buf1 of R0/R1 (h0(-1) = h1(-1) = 0) ----
    for (int idx = tid; idx < 4096; idx += NTHR) {
        smem[OFF_R0 + 4096 + idx] = 0.0f;
        smem[OFF_R1 + 4096 + idx] = 0.0f;
    }
    // ---- stage x(0) -> xbuf0, x(1) -> xbuf1 ----
    #pragma unroll
    for (int tt = 0; tt < 2; ++tt) {
        const float4* xp = (const float4*)&x[((size_t)tt*BATCH + b0 + b)*SDIM + wid*8];
        float4 xa = xp[0], xb2 = xp[1];
        float* xd = smem + OFF_X + tt*2048 + ((wid*4)*32 + b)*2;
        *(float2*)(xd      ) = make_float2(xa.x, xa.y);
        *(float2*)(xd +  64) = make_float2(xa.z, xa.w);
        *(float2*)(xd + 128) = make_float2(xb2.x, xb2.y);
        *(float2*)(xd + 192) = make_float2(xb2.z, xb2.w);
    }
    // ---- mbarrier init (count = 1: tid0's expect_tx arrival per phase) ----
    if (tid == 0) {
        asm volatile("mbarrier.init.shared.b64 [%0], 1;" :: "r"(mbA) : "memory");
        asm volatile("mbarrier.init.shared.b64 [%0], 1;" :: "r"(mbB) : "memory");
    }
    __syncthreads();
    cluster_sync();   // peers' mbars + buffers ready before any pushes
    if (tid == 0) {
        mbar_expect(mbA, 16384);   // phase 0 of A
        mbar_expect(mbB, 16384);   // phase 0 of B
    }

    // per-thread bias regs
    const u64* biasU = (const u64*)(smem + OFF_BIAS);
    const u64 bA0 = biasU[wid*4+0], bA1 = biasU[wid*4+1];
    const u64 bA2 = biasU[wid*4+2], bA3 = biasU[wid*4+3];
    const u64 bB0 = biasU[32+wid*4+0], bB1 = biasU[32+wid*4+1];
    const u64 bB2 = biasU[32+wid*4+2], bB3 = biasU[32+wid*4+3];
    const u64 houtb = (wid < 5) ? pack2(b_out[wid*2], b_out[wid*2+1]) : 0ull;

    const u32 wA    = sb + OFF_WA*4 + wid*6144;   // 96 kp x 64B
    const u32 wB    = sb + OFF_WB*4 + wid*8192;   // 128 kp x 64B
    const u32 lane8 = b * 8;
    const u32 regOff = (u32)(hs*8 + wid) * 256;   // warp's 256B slot in h regions

    float c00 = 0.f, c01 = 0.f, c10 = 0.f, c11 = 0.f;

    // ---- prologue: L0(0) from [h0(-1)=0 (buf1) | x(0) (xbuf0)], push A(0) ----
    {
        u64 a0 = bA0, a1 = bA1, a2 = bA2, a3 = bA3;
        gemm_blk<64>(wA,        sb + (OFF_R0 + 4096)*4 + lane8, a0, a1, a2, a3);
        gemm_blk<32>(wA + 4096, sb + OFF_X*4 + lane8,           a0, a1, a2, a3);
        float h00 = lstm_epi(a0, a1, c00);
        float h01 = lstm_epi(a2, a3, c01);
        u32 stg = sb + (OFF_STA + 0*512 + wid*64)*4;
        asm volatile("st.shared.b64 [%0], %1;" :: "r"(stg + lane8), "l"(pack2(h00, h01)) : "memory");
        __syncwarp();
        if (elect1())
            push_bulk(sb + OFF_R0*4 + regOff, stg, mbA);   // h0(0) -> r0 buf0
    }

    // ---- main loop ----
    for (int t = 0; t < T_STEPS; ++t) {
        const u32 par    = (u32)(t & 1);
        const u32 r0cur  = sb + (OFF_R0 + (t&1)*4096)*4;       // h0(t)
        const u32 r0next = sb + (OFF_R0 + ((t+1)&1)*4096)*4;   // h0(t+1) dest
        const u32 r1prev = sb + (OFF_R1 + ((t+1)&1)*4096)*4;   // h1(t-1)
        const u32 r1cur  = sb + (OFF_R1 + (t&1)*4096)*4;       // h1(t) dest
        const u32 xnext  = sb + (OFF_X  + ((t+1)&1)*2048)*4;   // x(t+1)

        mbar_wait(mbA, par);                  // h0(t) complete locally
        if (tid == 0 && t + 1 < T_STEPS) mbar_expect(mbA, 16384);

        // ---- L1(t): [h0(t) | h1(t-1)] ----
        {
            u64 a0 = bB0, a1 = bB1, a2 = bB2, a3 = bB3;
            gemm_blk<64>(wB,        r0cur  + lane8, a0, a1, a2, a3);
            gemm_blk<64>(wB + 4096, r1prev + lane8, a0, a1, a2, a3);
            float h10 = lstm_epi(a0, a1, c10);
            float h11 = lstm_epi(a2, a3, c11);
            u32 stg = sb + (OFF_STB + par*512 + wid*64)*4;
            asm volatile("st.shared.b64 [%0], %1;" :: "r"(stg + lane8), "l"(pack2(h10, h11)) : "memory");
            __syncwarp();
            if (elect1())
                push_bulk(r1cur + regOff, stg, mbB);
        }

        // ---- stage x(t+2) into xbuf[t&1] (x(t) is dead) ----
        if (t + 2 < T_STEPS) {
            const float4* xp = (const float4*)&x[((size_t)(t+2)*BATCH + b0 + b)*SDIM + wid*8];
            float4 xa = xp[0], xb2 = xp[1];
            float* xd = smem + OFF_X + (t&1)*2048 + ((wid*4)*32 + b)*2;
            *(float2*)(xd      ) = make_float2(xa.x, xa.y);
            *(float2*)(xd +  64) = make_float2(xa.z, xa.w);
            *(float2*)(xd + 128) = make_float2(xb2.x, xb2.y);
            *(float2*)(xd + 192) = make_float2(xb2.z, xb2.w);
        }
        __syncthreads();   // fences x staging for next iter's consumption

        // ---- L0(t+1): [h0(t) | x(t+1)] — hides the B round-trip ----
        if (t + 1 < T_STEPS) {
            u64 a0 = bA0, a1 = bA1, a2 = bA2, a3 = bA3;
            gemm_blk<64>(wA,        r0cur + lane8, a0, a1, a2, a3);
            gemm_blk<32>(wA + 4096, xnext + lane8, a0, a1, a2, a3);
            float h00 = lstm_epi(a0, a1, c00);
            float h01 = lstm_epi(a2, a3, c01);
            u32 stg = sb + (OFF_STA + ((t+1)&1)*512 + wid*64)*4;
            asm volatile("st.shared.b64 [%0], %1;" :: "r"(stg + lane8), "l"(pack2(h00, h01)) : "memory");
            __syncwarp();
            if (elect1())
                push_bulk(r0next + regOff, stg, mbA);
        }

        mbar_wait(mbB, par);                  // h1(t) complete locally
        if (tid == 0 && t + 1 < T_STEPS) mbar_expect(mbB, 16384);

        // ---- head(t): out = tanh(h1(t) @ W_out^T + b_out) ----
        if (wid < 5) {
            u64 acc = houtb;
            const u32 wo = sb + OFF_WO*4 + wid*8;
            #pragma unroll 8
            for (int kp = 0; kp < 64; ++kp) {
                float h0v, h1v;
                asm("ld.shared.v2.f32 {%0,%1}, [%2];" : "=f"(h0v), "=f"(h1v)
                    : "r"(r1cur + lane8 + kp*256));
                u64 w0, w1;
                asm("ld.shared.b64 %0, [%1];" : "=l"(w0) : "r"(wo + kp*80));
                asm("ld.shared.b64 %0, [%1];" : "=l"(w1) : "r"(wo + kp*80 + 40));
                acc = ffma2(w0, pack2(h0v, h0v), acc);
                acc = ffma2(w1, pack2(h1v, h1v), acc);
            }
            float o0, o1; unpack2(acc, o0, o1);
            float2 ov = make_float2(tanh_fast(o0), tanh_fast(o1));
            *(float2*)&out[((size_t)t*BATCH + b0 + b)*ADIM + wid*2] = ov;
        }
    }

    cluster_sync();   // all deliveries drained before any CTA exits
}

extern "C" void kernel_launch(void* const* d_in, const int* in_sizes, int n_in,
                              void* d_out, int out_size)
{
    const float* x    = (const float*)d_in[0];
    const float* Wih0 = (const float*)d_in[1];
    const float* Whh0 = (const float*)d_in[2];
    const float* bih0 = (const float*)d_in[3];
    const float* bhh0 = (const float*)d_in[4];
    const float* Wih1 = (const float*)d_in[5];
    const float* Whh1 = (const float*)d_in[6];
    const float* bih1 = (const float*)d_in[7];
    const float* bhh1 = (const float*)d_in[8];
    const float* Wout = (const float*)d_in[9];
    const float* bout = (const float*)d_in[10];
    float* out = (float*)d_out;

    cudaFuncSetAttribute(lstm_dsmem,
                         cudaFuncAttributeMaxDynamicSharedMemorySize, SMEM_BYTES);

    lstm_dsmem<<<NCTA, NTHR, SMEM_BYTES>>>(
        x, Wih0, Whh0, bih0, bhh0, Wih1, Whh1, bih1, bhh1, Wout, bout, out);
}